// round 2
// baseline (speedup 1.0000x reference)
#include <cuda_runtime.h>
#include <math.h>

// Problem dims (fixed by the dataset)
#define N_B 256
#define T_S 128
#define I_D 512
#define H_D 512
#define G4  2048            // 4*H
#define NT  32768           // N_B*T_S

// ---------------- scratch (static device memory; no runtime allocs) --------
__device__ float g_xw[(size_t)NT * G4];     // x@W_ih^T + bias, gate-permuted (256MB)
__device__ float g_hs[(size_t)NT * H_D];    // all h_t (64MB)
__device__ float g_h[2][N_B * H_D];         // ping-pong hidden state
__device__ float g_c[N_B * H_D];            // cell state
__device__ float g_Wih_t[I_D * G4];         // W_ih^T, gate-permuted cols
__device__ float g_Whh_t[H_D * G4];         // W_hh^T, gate-permuted cols
__device__ float g_Wout_t[H_D * H_D];       // W_out^T
__device__ float g_bias[G4];                // (b_ih+b_hh), gate-permuted

// ---------------- packed f32x2 FMA helpers ---------------------------------
__device__ __forceinline__ unsigned long long pack2(float x, float y) {
    unsigned long long r;
    asm("mov.b64 %0, {%1, %2};" : "=l"(r) : "f"(x), "f"(y));
    return r;
}
__device__ __forceinline__ void fma2u(unsigned long long &d,
                                      unsigned long long a,
                                      unsigned long long b) {
    asm("fma.rn.f32x2 %0, %1, %2, %0;" : "+l"(d) : "l"(a), "l"(b));
}
__device__ __forceinline__ float2 unpack2(unsigned long long v) {
    float2 r;
    asm("mov.b64 {%0, %1}, %2;" : "=f"(r.x), "=f"(r.y) : "l"(v));
    return r;
}

__device__ __forceinline__ float sigf(float x) { return 1.0f / (1.0f + expf(-x)); }

// ---------------- weight prep: transpose + gate-quadruple permutation ------
// permuted column p = 4*jh + g  <->  original gate row orig = g*H + jh
__global__ void prep_kernel(const float* __restrict__ W_ih,
                            const float* __restrict__ W_hh,
                            const float* __restrict__ b_ih,
                            const float* __restrict__ b_hh,
                            const float* __restrict__ W_out) {
    int i = blockIdx.x * blockDim.x + threadIdx.x;
    if (i < I_D * G4) {
        int k = i / G4, p = i % G4;
        int orig = (p & 3) * H_D + (p >> 2);
        g_Wih_t[i] = W_ih[(size_t)orig * I_D + k];
        g_Whh_t[i] = W_hh[(size_t)orig * H_D + k];
    }
    if (i < H_D * H_D) {
        int k = i / H_D, j = i % H_D;
        g_Wout_t[i] = W_out[(size_t)j * H_D + k];
    }
    if (i < G4) {
        int orig = (i & 3) * H_D + (i >> 2);
        g_bias[i] = b_ih[orig] + b_hh[orig];
    }
}

// ---------------- init h0, c0 from hx[:,0,:], cx[:,0,:] --------------------
__global__ void init_kernel(const float* __restrict__ hx,
                            const float* __restrict__ cx) {
    int i = blockIdx.x * blockDim.x + threadIdx.x;
    if (i < N_B * H_D) {
        int n = i / H_D, k = i % H_D;
        g_h[0][i] = hx[(size_t)n * T_S * H_D + k];
        g_c[i]    = cx[(size_t)n * T_S * H_D + k];
    }
}

// ---------------- pre-GEMM: g_xw = x @ Wih_t + bias (permuted cols) --------
// 128x128 tile, BK=16, 256 threads, 8x8 per thread via f32x2
__global__ __launch_bounds__(256) void gemm_xw_kernel(const float* __restrict__ x) {
    __shared__ float As[16][128];
    __shared__ float Bs[16][128];
    int tid = threadIdx.x;
    int m0 = blockIdx.y * 128;
    int n0 = blockIdx.x * 128;
    int ty = tid >> 4, tx = tid & 15;

    int arow = tid >> 2;          // 0..63 (second load +64)
    int akq  = (tid & 3) * 4;     // k offset 0,4,8,12
    int brow = tid >> 5;          // 0..7  (second load +8)
    int bcol = (tid & 31) * 4;    // 0..124

    unsigned long long acc[8][4] = {};

    for (int k0 = 0; k0 < I_D; k0 += 16) {
        float4 a0 = *(const float4*)(x + (size_t)(m0 + arow)      * I_D + k0 + akq);
        float4 a1 = *(const float4*)(x + (size_t)(m0 + arow + 64) * I_D + k0 + akq);
        float4 b0 = *(const float4*)(g_Wih_t + (size_t)(k0 + brow)     * G4 + n0 + bcol);
        float4 b1 = *(const float4*)(g_Wih_t + (size_t)(k0 + brow + 8) * G4 + n0 + bcol);
        __syncthreads();
        As[akq + 0][arow] = a0.x; As[akq + 1][arow] = a0.y;
        As[akq + 2][arow] = a0.z; As[akq + 3][arow] = a0.w;
        As[akq + 0][arow + 64] = a1.x; As[akq + 1][arow + 64] = a1.y;
        As[akq + 2][arow + 64] = a1.z; As[akq + 3][arow + 64] = a1.w;
        *(float4*)&Bs[brow][bcol]     = b0;
        *(float4*)&Bs[brow + 8][bcol] = b1;
        __syncthreads();
#pragma unroll
        for (int kk = 0; kk < 16; kk++) {
            float4 aA = *(float4*)&As[kk][ty * 8];
            float4 aB = *(float4*)&As[kk][ty * 8 + 4];
            float4 bA = *(float4*)&Bs[kk][tx * 8];
            float4 bB = *(float4*)&Bs[kk][tx * 8 + 4];
            unsigned long long bp0 = pack2(bA.x, bA.y);
            unsigned long long bp1 = pack2(bA.z, bA.w);
            unsigned long long bp2 = pack2(bB.x, bB.y);
            unsigned long long bp3 = pack2(bB.z, bB.w);
            float av[8] = {aA.x, aA.y, aA.z, aA.w, aB.x, aB.y, aB.z, aB.w};
#pragma unroll
            for (int i = 0; i < 8; i++) {
                unsigned long long ap = pack2(av[i], av[i]);
                fma2u(acc[i][0], ap, bp0);
                fma2u(acc[i][1], ap, bp1);
                fma2u(acc[i][2], ap, bp2);
                fma2u(acc[i][3], ap, bp3);
            }
        }
    }
#pragma unroll
    for (int i = 0; i < 8; i++) {
        int m = m0 + ty * 8 + i;
#pragma unroll
        for (int j = 0; j < 4; j++) {
            float2 v = unpack2(acc[i][j]);
            int c = n0 + tx * 8 + j * 2;
            v.x += g_bias[c];
            v.y += g_bias[c + 1];
            *(float2*)&g_xw[(size_t)m * G4 + c] = v;
        }
    }
}

// ---------------- one LSTM timestep (fused gemm + cell) --------------------
// gates = (h*r) @ Whh_t + g_xw[:,t,:]; tile 64(batch) x 64(gate-cols), 4x4/thread
__global__ __launch_bounds__(256) void lstm_step_kernel(const int* __restrict__ is_init, int t) {
    __shared__ float As[16][64];
    __shared__ float Bs[16][64];
    const float* hin  = g_h[t & 1];
    float*       hout = g_h[(t + 1) & 1];
    int tid = threadIdx.x;
    int c0 = blockIdx.x * 64;   // gate cols (permuted)
    int n0 = blockIdx.y * 64;   // batch
    int ty = tid >> 4, tx = tid & 15;

    int arow = tid >> 2;          // 0..63
    int akq  = (tid & 3) * 4;
    int brow = tid >> 4;          // 0..15
    int bcol = (tid & 15) * 4;

    int an = n0 + arow;
    float rr_a = 1.0f - (float)is_init[an * T_S + t];

    unsigned long long acc[4][2] = {};

    for (int k0 = 0; k0 < H_D; k0 += 16) {
        float4 a = *(const float4*)(hin + (size_t)an * H_D + k0 + akq);
        float4 b = *(const float4*)(g_Whh_t + (size_t)(k0 + brow) * G4 + c0 + bcol);
        __syncthreads();
        As[akq + 0][arow] = a.x * rr_a;
        As[akq + 1][arow] = a.y * rr_a;
        As[akq + 2][arow] = a.z * rr_a;
        As[akq + 3][arow] = a.w * rr_a;
        *(float4*)&Bs[brow][bcol] = b;
        __syncthreads();
#pragma unroll
        for (int kk = 0; kk < 16; kk++) {
            float4 av = *(float4*)&As[kk][ty * 4];
            float4 bv = *(float4*)&Bs[kk][tx * 4];
            unsigned long long bp0 = pack2(bv.x, bv.y);
            unsigned long long bp1 = pack2(bv.z, bv.w);
            float aa[4] = {av.x, av.y, av.z, av.w};
#pragma unroll
            for (int i = 0; i < 4; i++) {
                unsigned long long ap = pack2(aa[i], aa[i]);
                fma2u(acc[i][0], ap, bp0);
                fma2u(acc[i][1], ap, bp1);
            }
        }
    }

    int c  = c0 + tx * 4;   // permuted col of the i-gate; quad = (i,f,g,o)
    int jh = c >> 2;        // hidden unit
#pragma unroll
    for (int i = 0; i < 4; i++) {
        int n = n0 + ty * 4 + i;
        float rr = 1.0f - (float)is_init[n * T_S + t];
        float4 xw = *(const float4*)&g_xw[(size_t)(n * T_S + t) * G4 + c];
        float2 g01 = unpack2(acc[i][0]);
        float2 g23 = unpack2(acc[i][1]);
        float gi = g01.x + xw.x;
        float gf = g01.y + xw.y;
        float gg = g23.x + xw.z;
        float go = g23.y + xw.w;
        float cold = g_c[n * H_D + jh] * rr;
        float cn = sigf(gf) * cold + sigf(gi) * tanhf(gg);
        float hn = sigf(go) * tanhf(cn);
        g_c[n * H_D + jh]  = cn;
        hout[n * H_D + jh] = hn;
        g_hs[(size_t)(n * T_S + t) * H_D + jh] = hn;
    }
}

// ---------------- output GEMM: out = mish(hs @ Wout_t + b_out) -------------
__global__ __launch_bounds__(256) void gemm_out_kernel(const float* __restrict__ b_out,
                                                       float* __restrict__ out) {
    __shared__ float As[16][128];
    __shared__ float Bs[16][128];
    int tid = threadIdx.x;
    int m0 = blockIdx.y * 128;
    int n0 = blockIdx.x * 128;
    int ty = tid >> 4, tx = tid & 15;

    int arow = tid >> 2;
    int akq  = (tid & 3) * 4;
    int brow = tid >> 5;
    int bcol = (tid & 31) * 4;

    unsigned long long acc[8][4] = {};

    for (int k0 = 0; k0 < H_D; k0 += 16) {
        float4 a0 = *(const float4*)(g_hs + (size_t)(m0 + arow)      * H_D + k0 + akq);
        float4 a1 = *(const float4*)(g_hs + (size_t)(m0 + arow + 64) * H_D + k0 + akq);
        float4 b0 = *(const float4*)(g_Wout_t + (size_t)(k0 + brow)     * H_D + n0 + bcol);
        float4 b1 = *(const float4*)(g_Wout_t + (size_t)(k0 + brow + 8) * H_D + n0 + bcol);
        __syncthreads();
        As[akq + 0][arow] = a0.x; As[akq + 1][arow] = a0.y;
        As[akq + 2][arow] = a0.z; As[akq + 3][arow] = a0.w;
        As[akq + 0][arow + 64] = a1.x; As[akq + 1][arow + 64] = a1.y;
        As[akq + 2][arow + 64] = a1.z; As[akq + 3][arow + 64] = a1.w;
        *(float4*)&Bs[brow][bcol]     = b0;
        *(float4*)&Bs[brow + 8][bcol] = b1;
        __syncthreads();
#pragma unroll
        for (int kk = 0; kk < 16; kk++) {
            float4 aA = *(float4*)&As[kk][ty * 8];
            float4 aB = *(float4*)&As[kk][ty * 8 + 4];
            float4 bA = *(float4*)&Bs[kk][tx * 8];
            float4 bB = *(float4*)&Bs[kk][tx * 8 + 4];
            unsigned long long bp0 = pack2(bA.x, bA.y);
            unsigned long long bp1 = pack2(bA.z, bA.w);
            unsigned long long bp2 = pack2(bB.x, bB.y);
            unsigned long long bp3 = pack2(bB.z, bB.w);
            float av[8] = {aA.x, aA.y, aA.z, aA.w, aB.x, aB.y, aB.z, aB.w};
#pragma unroll
            for (int i = 0; i < 8; i++) {
                unsigned long long ap = pack2(av[i], av[i]);
                fma2u(acc[i][0], ap, bp0);
                fma2u(acc[i][1], ap, bp1);
                fma2u(acc[i][2], ap, bp2);
                fma2u(acc[i][3], ap, bp3);
            }
        }
    }
#pragma unroll
    for (int i = 0; i < 8; i++) {
        int m = m0 + ty * 8 + i;
#pragma unroll
        for (int j = 0; j < 4; j++) {
            float2 v = unpack2(acc[i][j]);
            int c = n0 + tx * 8 + j * 2;
            float v0 = v.x + b_out[c];
            float v1 = v.y + b_out[c + 1];
            // mish(x) = x * tanh(log1p(exp(x)))
            float o0 = v0 * tanhf(log1pf(expf(v0)));
            float o1 = v1 * tanhf(log1pf(expf(v1)));
            out[(size_t)m * H_D + c]     = o0;
            out[(size_t)m * H_D + c + 1] = o1;
        }
    }
}

// ---------------- broadcast hT, cT to [N,T,H] -------------------------------
__global__ void bcast_kernel(float* __restrict__ out) {
    int i = blockIdx.x * blockDim.x + threadIdx.x;   // over NT*H_D/4 float4s
    if (i < NT * H_D / 4) {
        int row = i >> 7;      // H_D/4 = 128 float4 per row; row = n*T+t
        int f4  = i & 127;
        int n   = row >> 7;    // T = 128
        float4 hv = *(const float4*)&g_h[0][n * H_D + f4 * 4];  // final h lives in buf 0 (T even)
        float4 cv = *(const float4*)&g_c[n * H_D + f4 * 4];
        float4* o = (float4*)out;
        o[(size_t)(NT * H_D / 4) + i]     = hv;
        o[(size_t)(NT * H_D / 4) * 2 + i] = cv;
    }
}

// ---------------- launch ----------------------------------------------------
extern "C" void kernel_launch(void* const* d_in, const int* in_sizes, int n_in,
                              void* d_out, int out_size) {
    const float* x      = (const float*)d_in[0];
    const int*   isinit = (const int*)  d_in[1];
    const float* hx     = (const float*)d_in[2];
    const float* cx     = (const float*)d_in[3];
    const float* W_ih   = (const float*)d_in[4];
    const float* W_hh   = (const float*)d_in[5];
    const float* b_ih   = (const float*)d_in[6];
    const float* b_hh   = (const float*)d_in[7];
    const float* W_out  = (const float*)d_in[8];
    const float* b_out  = (const float*)d_in[9];
    float* out = (float*)d_out;

    prep_kernel<<<(I_D * G4 + 255) / 256, 256>>>(W_ih, W_hh, b_ih, b_hh, W_out);
    init_kernel<<<(N_B * H_D + 255) / 256, 256>>>(hx, cx);

    { dim3 g(G4 / 128, NT / 128); gemm_xw_kernel<<<g, 256>>>(x); }

    for (int t = 0; t < T_S; t++) {
        dim3 g(G4 / 64, N_B / 64);
        lstm_step_kernel<<<g, 256>>>(isinit, t);
    }

    { dim3 g(H_D / 128, NT / 128); gemm_out_kernel<<<g, 256>>>(b_out, out); }

    bcast_kernel<<<(NT * H_D / 4 + 255) / 256, 256>>>(out);
}

// round 3
// speedup vs baseline: 1.0373x; 1.0373x over previous
#include <cuda_runtime.h>
#include <math.h>

// Problem dims (fixed by the dataset)
#define N_B 256
#define T_S 128
#define I_D 512
#define H_D 512
#define G4  2048            // 4*H
#define NT  32768           // N_B*T_S

// ---------------- scratch (static device memory; no runtime allocs) --------
__device__ float g_xw[(size_t)NT * G4];     // x@W_ih^T + bias, gate-permuted (256MB)
__device__ float g_hs[(size_t)NT * H_D];    // all h_t (64MB)
__device__ float g_h[2][N_B * H_D];         // ping-pong hidden state
__device__ float g_c[N_B * H_D];            // cell state
__device__ float g_Wih_t[I_D * G4];         // W_ih^T, gate-permuted cols
__device__ float g_Whh_t[H_D * G4];         // W_hh^T, gate-permuted cols
__device__ float g_Wout_t[H_D * H_D];       // W_out^T
__device__ float g_bias[G4];                // (b_ih+b_hh), gate-permuted

// ---------------- packed f32x2 FMA helpers ---------------------------------
__device__ __forceinline__ unsigned long long pack2(float x, float y) {
    unsigned long long r;
    asm("mov.b64 %0, {%1, %2};" : "=l"(r) : "f"(x), "f"(y));
    return r;
}
__device__ __forceinline__ void fma2u(unsigned long long &d,
                                      unsigned long long a,
                                      unsigned long long b) {
    asm("fma.rn.f32x2 %0, %1, %2, %0;" : "+l"(d) : "l"(a), "l"(b));
}
__device__ __forceinline__ float2 unpack2(unsigned long long v) {
    float2 r;
    asm("mov.b64 {%0, %1}, %2;" : "=f"(r.x), "=f"(r.y) : "l"(v));
    return r;
}

__device__ __forceinline__ float sigf(float x) { return 1.0f / (1.0f + expf(-x)); }

// ---------------- weight prep: transpose + gate-quadruple permutation ------
// permuted column p = 4*jh + g  <->  original gate row orig = g*H + jh
__global__ void prep_kernel(const float* __restrict__ W_ih,
                            const float* __restrict__ W_hh,
                            const float* __restrict__ b_ih,
                            const float* __restrict__ b_hh,
                            const float* __restrict__ W_out) {
    int i = blockIdx.x * blockDim.x + threadIdx.x;
    if (i < I_D * G4) {
        int k = i / G4, p = i % G4;
        int orig = (p & 3) * H_D + (p >> 2);
        g_Wih_t[i] = W_ih[(size_t)orig * I_D + k];
        g_Whh_t[i] = W_hh[(size_t)orig * H_D + k];
    }
    if (i < H_D * H_D) {
        int k = i / H_D, j = i % H_D;
        g_Wout_t[i] = W_out[(size_t)j * H_D + k];
    }
    if (i < G4) {
        int orig = (i & 3) * H_D + (i >> 2);
        g_bias[i] = b_ih[orig] + b_hh[orig];
    }
}

// ---------------- init h0, c0 from hx[:,0,:], cx[:,0,:] --------------------
__global__ void init_kernel(const float* __restrict__ hx,
                            const float* __restrict__ cx) {
    int i = blockIdx.x * blockDim.x + threadIdx.x;
    if (i < N_B * H_D) {
        int n = i / H_D, k = i % H_D;
        g_h[0][i] = hx[(size_t)n * T_S * H_D + k];
        g_c[i]    = cx[(size_t)n * T_S * H_D + k];
    }
}

// ---------------- pre-GEMM: g_xw = x @ Wih_t + bias (permuted cols) --------
// 128x128 tile, BK=16, 256 threads, 8x8 per thread via f32x2
__global__ __launch_bounds__(256) void gemm_xw_kernel(const float* __restrict__ x) {
    __shared__ float As[16][128];
    __shared__ float Bs[16][128];
    int tid = threadIdx.x;
    int m0 = blockIdx.y * 128;
    int n0 = blockIdx.x * 128;
    int ty = tid >> 4, tx = tid & 15;

    int arow = tid >> 2;          // 0..63 (second load +64)
    int akq  = (tid & 3) * 4;     // k offset 0,4,8,12
    int brow = tid >> 5;          // 0..7  (second load +8)
    int bcol = (tid & 31) * 4;    // 0..124

    unsigned long long acc[8][4] = {};

    for (int k0 = 0; k0 < I_D; k0 += 16) {
        float4 a0 = *(const float4*)(x + (size_t)(m0 + arow)      * I_D + k0 + akq);
        float4 a1 = *(const float4*)(x + (size_t)(m0 + arow + 64) * I_D + k0 + akq);
        float4 b0 = *(const float4*)(g_Wih_t + (size_t)(k0 + brow)     * G4 + n0 + bcol);
        float4 b1 = *(const float4*)(g_Wih_t + (size_t)(k0 + brow + 8) * G4 + n0 + bcol);
        __syncthreads();
        As[akq + 0][arow] = a0.x; As[akq + 1][arow] = a0.y;
        As[akq + 2][arow] = a0.z; As[akq + 3][arow] = a0.w;
        As[akq + 0][arow + 64] = a1.x; As[akq + 1][arow + 64] = a1.y;
        As[akq + 2][arow + 64] = a1.z; As[akq + 3][arow + 64] = a1.w;
        *(float4*)&Bs[brow][bcol]     = b0;
        *(float4*)&Bs[brow + 8][bcol] = b1;
        __syncthreads();
#pragma unroll
        for (int kk = 0; kk < 16; kk++) {
            float4 aA = *(float4*)&As[kk][ty * 8];
            float4 aB = *(float4*)&As[kk][ty * 8 + 4];
            float4 bA = *(float4*)&Bs[kk][tx * 8];
            float4 bB = *(float4*)&Bs[kk][tx * 8 + 4];
            unsigned long long bp0 = pack2(bA.x, bA.y);
            unsigned long long bp1 = pack2(bA.z, bA.w);
            unsigned long long bp2 = pack2(bB.x, bB.y);
            unsigned long long bp3 = pack2(bB.z, bB.w);
            float av[8] = {aA.x, aA.y, aA.z, aA.w, aB.x, aB.y, aB.z, aB.w};
#pragma unroll
            for (int i = 0; i < 8; i++) {
                unsigned long long ap = pack2(av[i], av[i]);
                fma2u(acc[i][0], ap, bp0);
                fma2u(acc[i][1], ap, bp1);
                fma2u(acc[i][2], ap, bp2);
                fma2u(acc[i][3], ap, bp3);
            }
        }
    }
#pragma unroll
    for (int i = 0; i < 8; i++) {
        int m = m0 + ty * 8 + i;
#pragma unroll
        for (int j = 0; j < 4; j++) {
            float2 v = unpack2(acc[i][j]);
            int c = n0 + tx * 8 + j * 2;
            v.x += g_bias[c];
            v.y += g_bias[c + 1];
            *(float2*)&g_xw[(size_t)m * G4 + c] = v;
        }
    }
}

// ---------------- one LSTM timestep (fused gemm + cell) --------------------
// gates = (h*r) @ Whh_t + g_xw[:,t,:]; tile 64(batch) x 64(gate-cols), 4x4/thread
__global__ __launch_bounds__(256) void lstm_step_kernel(const int* __restrict__ is_init, int t) {
    __shared__ float As[16][64];
    __shared__ float Bs[16][64];
    const float* hin  = g_h[t & 1];
    float*       hout = g_h[(t + 1) & 1];
    int tid = threadIdx.x;
    int c0 = blockIdx.x * 64;   // gate cols (permuted)
    int n0 = blockIdx.y * 64;   // batch
    int ty = tid >> 4, tx = tid & 15;

    int arow = tid >> 2;          // 0..63
    int akq  = (tid & 3) * 4;
    int brow = tid >> 4;          // 0..15
    int bcol = (tid & 15) * 4;

    int an = n0 + arow;
    float rr_a = 1.0f - (float)is_init[an * T_S + t];

    unsigned long long acc[4][2] = {};

    for (int k0 = 0; k0 < H_D; k0 += 16) {
        float4 a = *(const float4*)(hin + (size_t)an * H_D + k0 + akq);
        float4 b = *(const float4*)(g_Whh_t + (size_t)(k0 + brow) * G4 + c0 + bcol);
        __syncthreads();
        As[akq + 0][arow] = a.x * rr_a;
        As[akq + 1][arow] = a.y * rr_a;
        As[akq + 2][arow] = a.z * rr_a;
        As[akq + 3][arow] = a.w * rr_a;
        *(float4*)&Bs[brow][bcol] = b;
        __syncthreads();
#pragma unroll
        for (int kk = 0; kk < 16; kk++) {
            float4 av = *(float4*)&As[kk][ty * 4];
            float4 bv = *(float4*)&Bs[kk][tx * 4];
            unsigned long long bp0 = pack2(bv.x, bv.y);
            unsigned long long bp1 = pack2(bv.z, bv.w);
            float aa[4] = {av.x, av.y, av.z, av.w};
#pragma unroll
            for (int i = 0; i < 4; i++) {
                unsigned long long ap = pack2(aa[i], aa[i]);
                fma2u(acc[i][0], ap, bp0);
                fma2u(acc[i][1], ap, bp1);
            }
        }
    }

    int c  = c0 + tx * 4;   // permuted col of the i-gate; quad = (i,f,g,o)
    int jh = c >> 2;        // hidden unit
#pragma unroll
    for (int i = 0; i < 4; i++) {
        int n = n0 + ty * 4 + i;
        float rr = 1.0f - (float)is_init[n * T_S + t];
        float4 xw = *(const float4*)&g_xw[(size_t)(n * T_S + t) * G4 + c];
        float2 g01 = unpack2(acc[i][0]);
        float2 g23 = unpack2(acc[i][1]);
        float gi = g01.x + xw.x;
        float gf = g01.y + xw.y;
        float gg = g23.x + xw.z;
        float go = g23.y + xw.w;
        float cold = g_c[n * H_D + jh] * rr;
        float cn = sigf(gf) * cold + sigf(gi) * tanhf(gg);
        float hn = sigf(go) * tanhf(cn);
        g_c[n * H_D + jh]  = cn;
        hout[n * H_D + jh] = hn;
        g_hs[(size_t)(n * T_S + t) * H_D + jh] = hn;
    }
}

// ---------------- output GEMM: out = mish(hs @ Wout_t + b_out) -------------
__global__ __launch_bounds__(256) void gemm_out_kernel(const float* __restrict__ b_out,
                                                       float* __restrict__ out) {
    __shared__ float As[16][128];
    __shared__ float Bs[16][128];
    int tid = threadIdx.x;
    int m0 = blockIdx.y * 128;
    int n0 = blockIdx.x * 128;
    int ty = tid >> 4, tx = tid & 15;

    int arow = tid >> 2;
    int akq  = (tid & 3) * 4;
    int brow = tid >> 5;
    int bcol = (tid & 31) * 4;

    unsigned long long acc[8][4] = {};

    for (int k0 = 0; k0 < H_D; k0 += 16) {
        float4 a0 = *(const float4*)(g_hs + (size_t)(m0 + arow)      * H_D + k0 + akq);
        float4 a1 = *(const float4*)(g_hs + (size_t)(m0 + arow + 64) * H_D + k0 + akq);
        float4 b0 = *(const float4*)(g_Wout_t + (size_t)(k0 + brow)     * H_D + n0 + bcol);
        float4 b1 = *(const float4*)(g_Wout_t + (size_t)(k0 + brow + 8) * H_D + n0 + bcol);
        __syncthreads();
        As[akq + 0][arow] = a0.x; As[akq + 1][arow] = a0.y;
        As[akq + 2][arow] = a0.z; As[akq + 3][arow] = a0.w;
        As[akq + 0][arow + 64] = a1.x; As[akq + 1][arow + 64] = a1.y;
        As[akq + 2][arow + 64] = a1.z; As[akq + 3][arow + 64] = a1.w;
        *(float4*)&Bs[brow][bcol]     = b0;
        *(float4*)&Bs[brow + 8][bcol] = b1;
        __syncthreads();
#pragma unroll
        for (int kk = 0; kk < 16; kk++) {
            float4 aA = *(float4*)&As[kk][ty * 8];
            float4 aB = *(float4*)&As[kk][ty * 8 + 4];
            float4 bA = *(float4*)&Bs[kk][tx * 8];
            float4 bB = *(float4*)&Bs[kk][tx * 8 + 4];
            unsigned long long bp0 = pack2(bA.x, bA.y);
            unsigned long long bp1 = pack2(bA.z, bA.w);
            unsigned long long bp2 = pack2(bB.x, bB.y);
            unsigned long long bp3 = pack2(bB.z, bB.w);
            float av[8] = {aA.x, aA.y, aA.z, aA.w, aB.x, aB.y, aB.z, aB.w};
#pragma unroll
            for (int i = 0; i < 8; i++) {
                unsigned long long ap = pack2(av[i], av[i]);
                fma2u(acc[i][0], ap, bp0);
                fma2u(acc[i][1], ap, bp1);
                fma2u(acc[i][2], ap, bp2);
                fma2u(acc[i][3], ap, bp3);
            }
        }
    }
#pragma unroll
    for (int i = 0; i < 8; i++) {
        int m = m0 + ty * 8 + i;
#pragma unroll
        for (int j = 0; j < 4; j++) {
            float2 v = unpack2(acc[i][j]);
            int c = n0 + tx * 8 + j * 2;
            float v0 = v.x + b_out[c];
            float v1 = v.y + b_out[c + 1];
            // mish(x) = x * tanh(log1p(exp(x)))
            float o0 = v0 * tanhf(log1pf(expf(v0)));
            float o1 = v1 * tanhf(log1pf(expf(v1)));
            out[(size_t)m * H_D + c]     = o0;
            out[(size_t)m * H_D + c + 1] = o1;
        }
    }
}

// ---------------- broadcast hT, cT to [N,T,H] -------------------------------
__global__ void bcast_kernel(float* __restrict__ out) {
    int i = blockIdx.x * blockDim.x + threadIdx.x;   // over NT*H_D/4 float4s
    if (i < NT * H_D / 4) {
        int row = i >> 7;      // H_D/4 = 128 float4 per row; row = n*T+t
        int f4  = i & 127;
        int n   = row >> 7;    // T = 128
        float4 hv = *(const float4*)&g_h[0][n * H_D + f4 * 4];  // final h lives in buf 0 (T even)
        float4 cv = *(const float4*)&g_c[n * H_D + f4 * 4];
        float4* o = (float4*)out;
        o[(size_t)(NT * H_D / 4) + i]     = hv;
        o[(size_t)(NT * H_D / 4) * 2 + i] = cv;
    }
}

// ---------------- launch ----------------------------------------------------
extern "C" void kernel_launch(void* const* d_in, const int* in_sizes, int n_in,
                              void* d_out, int out_size) {
    const float* x      = (const float*)d_in[0];
    const int*   isinit = (const int*)  d_in[1];
    const float* hx     = (const float*)d_in[2];
    const float* cx     = (const float*)d_in[3];
    const float* W_ih   = (const float*)d_in[4];
    const float* W_hh   = (const float*)d_in[5];
    const float* b_ih   = (const float*)d_in[6];
    const float* b_hh   = (const float*)d_in[7];
    const float* W_out  = (const float*)d_in[8];
    const float* b_out  = (const float*)d_in[9];
    float* out = (float*)d_out;

    prep_kernel<<<(I_D * G4 + 255) / 256, 256>>>(W_ih, W_hh, b_ih, b_hh, W_out);
    init_kernel<<<(N_B * H_D + 255) / 256, 256>>>(hx, cx);

    { dim3 g(G4 / 128, NT / 128); gemm_xw_kernel<<<g, 256>>>(x); }

    for (int t = 0; t < T_S; t++) {
        dim3 g(G4 / 64, N_B / 64);
        lstm_step_kernel<<<g, 256>>>(isinit, t);
    }

    { dim3 g(H_D / 128, NT / 128); gemm_out_kernel<<<g, 256>>>(b_out, out); }

    bcast_kernel<<<(NT * H_D / 4 + 255) / 256, 256>>>(out);
}

// round 4
// speedup vs baseline: 1.0389x; 1.0016x over previous
#include <cuda_runtime.h>
#include <math.h>

// Problem dims (fixed by the dataset)
#define N_B 256
#define T_S 128
#define I_D 512
#define H_D 512
#define G4  2048            // 4*H
#define NT  32768           // N_B*T_S

// ---------------- scratch (static device memory; no runtime allocs) --------
__device__ float g_xw[(size_t)NT * G4];     // x@W_ih^T + bias, gate-permuted (256MB)
__device__ float g_hs[(size_t)NT * H_D];    // all h_t (64MB)
__device__ float g_h[2][N_B * H_D];         // ping-pong hidden state
__device__ float g_c[N_B * H_D];            // cell state
__device__ float g_Wih_t[I_D * G4];         // W_ih^T, gate-permuted cols
__device__ float g_Whh_t[H_D * G4];         // W_hh^T, gate-permuted cols
__device__ float g_Wout_t[H_D * H_D];       // W_out^T
__device__ float g_bias[G4];                // (b_ih+b_hh), gate-permuted

// ---------------- packed f32x2 FMA helpers ---------------------------------
__device__ __forceinline__ unsigned long long pack2(float x, float y) {
    unsigned long long r;
    asm("mov.b64 %0, {%1, %2};" : "=l"(r) : "f"(x), "f"(y));
    return r;
}
__device__ __forceinline__ void fma2u(unsigned long long &d,
                                      unsigned long long a,
                                      unsigned long long b) {
    asm("fma.rn.f32x2 %0, %1, %2, %0;" : "+l"(d) : "l"(a), "l"(b));
}
__device__ __forceinline__ float2 unpack2(unsigned long long v) {
    float2 r;
    asm("mov.b64 {%0, %1}, %2;" : "=f"(r.x), "=f"(r.y) : "l"(v));
    return r;
}

__device__ __forceinline__ float sigf(float x) { return 1.0f / (1.0f + expf(-x)); }

// ---------------- weight prep: transpose + gate-quadruple permutation ------
// permuted column p = 4*jh + g  <->  original gate row orig = g*H + jh
__global__ void prep_kernel(const float* __restrict__ W_ih,
                            const float* __restrict__ W_hh,
                            const float* __restrict__ b_ih,
                            const float* __restrict__ b_hh,
                            const float* __restrict__ W_out) {
    int i = blockIdx.x * blockDim.x + threadIdx.x;
    if (i < I_D * G4) {
        int k = i / G4, p = i % G4;
        int orig = (p & 3) * H_D + (p >> 2);
        g_Wih_t[i] = W_ih[(size_t)orig * I_D + k];
        g_Whh_t[i] = W_hh[(size_t)orig * H_D + k];
    }
    if (i < H_D * H_D) {
        int k = i / H_D, j = i % H_D;
        g_Wout_t[i] = W_out[(size_t)j * H_D + k];
    }
    if (i < G4) {
        int orig = (i & 3) * H_D + (i >> 2);
        g_bias[i] = b_ih[orig] + b_hh[orig];
    }
}

// ---------------- init h0, c0 from hx[:,0,:], cx[:,0,:] --------------------
__global__ void init_kernel(const float* __restrict__ hx,
                            const float* __restrict__ cx) {
    int i = blockIdx.x * blockDim.x + threadIdx.x;
    if (i < N_B * H_D) {
        int n = i / H_D, k = i % H_D;
        g_h[0][i] = hx[(size_t)n * T_S * H_D + k];
        g_c[i]    = cx[(size_t)n * T_S * H_D + k];
    }
}

// ---------------- pre-GEMM: g_xw = x @ Wih_t + bias (permuted cols) --------
// 128x128 tile, BK=16, 256 threads, 8x8 per thread via f32x2
__global__ __launch_bounds__(256) void gemm_xw_kernel(const float* __restrict__ x) {
    __shared__ float As[16][128];
    __shared__ float Bs[16][128];
    int tid = threadIdx.x;
    int m0 = blockIdx.y * 128;
    int n0 = blockIdx.x * 128;
    int ty = tid >> 4, tx = tid & 15;

    int arow = tid >> 2;          // 0..63 (second load +64)
    int akq  = (tid & 3) * 4;     // k offset 0,4,8,12
    int brow = tid >> 5;          // 0..7  (second load +8)
    int bcol = (tid & 31) * 4;    // 0..124

    unsigned long long acc[8][4] = {};

    for (int k0 = 0; k0 < I_D; k0 += 16) {
        float4 a0 = *(const float4*)(x + (size_t)(m0 + arow)      * I_D + k0 + akq);
        float4 a1 = *(const float4*)(x + (size_t)(m0 + arow + 64) * I_D + k0 + akq);
        float4 b0 = *(const float4*)(g_Wih_t + (size_t)(k0 + brow)     * G4 + n0 + bcol);
        float4 b1 = *(const float4*)(g_Wih_t + (size_t)(k0 + brow + 8) * G4 + n0 + bcol);
        __syncthreads();
        As[akq + 0][arow] = a0.x; As[akq + 1][arow] = a0.y;
        As[akq + 2][arow] = a0.z; As[akq + 3][arow] = a0.w;
        As[akq + 0][arow + 64] = a1.x; As[akq + 1][arow + 64] = a1.y;
        As[akq + 2][arow + 64] = a1.z; As[akq + 3][arow + 64] = a1.w;
        *(float4*)&Bs[brow][bcol]     = b0;
        *(float4*)&Bs[brow + 8][bcol] = b1;
        __syncthreads();
#pragma unroll
        for (int kk = 0; kk < 16; kk++) {
            float4 aA = *(float4*)&As[kk][ty * 8];
            float4 aB = *(float4*)&As[kk][ty * 8 + 4];
            float4 bA = *(float4*)&Bs[kk][tx * 8];
            float4 bB = *(float4*)&Bs[kk][tx * 8 + 4];
            unsigned long long bp0 = pack2(bA.x, bA.y);
            unsigned long long bp1 = pack2(bA.z, bA.w);
            unsigned long long bp2 = pack2(bB.x, bB.y);
            unsigned long long bp3 = pack2(bB.z, bB.w);
            float av[8] = {aA.x, aA.y, aA.z, aA.w, aB.x, aB.y, aB.z, aB.w};
#pragma unroll
            for (int i = 0; i < 8; i++) {
                unsigned long long ap = pack2(av[i], av[i]);
                fma2u(acc[i][0], ap, bp0);
                fma2u(acc[i][1], ap, bp1);
                fma2u(acc[i][2], ap, bp2);
                fma2u(acc[i][3], ap, bp3);
            }
        }
    }
#pragma unroll
    for (int i = 0; i < 8; i++) {
        int m = m0 + ty * 8 + i;
#pragma unroll
        for (int j = 0; j < 4; j++) {
            float2 v = unpack2(acc[i][j]);
            int c = n0 + tx * 8 + j * 2;
            v.x += g_bias[c];
            v.y += g_bias[c + 1];
            *(float2*)&g_xw[(size_t)m * G4 + c] = v;
        }
    }
}

// ---------------- one LSTM timestep (fused gemm + cell) --------------------
// gates = (h*r) @ Whh_t + g_xw[:,t,:]; tile 64(batch) x 64(gate-cols), 4x4/thread
__global__ __launch_bounds__(256) void lstm_step_kernel(const int* __restrict__ is_init, int t) {
    __shared__ float As[16][64];
    __shared__ float Bs[16][64];
    const float* hin  = g_h[t & 1];
    float*       hout = g_h[(t + 1) & 1];
    int tid = threadIdx.x;
    int c0 = blockIdx.x * 64;   // gate cols (permuted)
    int n0 = blockIdx.y * 64;   // batch
    int ty = tid >> 4, tx = tid & 15;

    int arow = tid >> 2;          // 0..63
    int akq  = (tid & 3) * 4;
    int brow = tid >> 4;          // 0..15
    int bcol = (tid & 15) * 4;

    int an = n0 + arow;
    float rr_a = 1.0f - (float)is_init[an * T_S + t];

    unsigned long long acc[4][2] = {};

    for (int k0 = 0; k0 < H_D; k0 += 16) {
        float4 a = *(const float4*)(hin + (size_t)an * H_D + k0 + akq);
        float4 b = *(const float4*)(g_Whh_t + (size_t)(k0 + brow) * G4 + c0 + bcol);
        __syncthreads();
        As[akq + 0][arow] = a.x * rr_a;
        As[akq + 1][arow] = a.y * rr_a;
        As[akq + 2][arow] = a.z * rr_a;
        As[akq + 3][arow] = a.w * rr_a;
        *(float4*)&Bs[brow][bcol] = b;
        __syncthreads();
#pragma unroll
        for (int kk = 0; kk < 16; kk++) {
            float4 av = *(float4*)&As[kk][ty * 4];
            float4 bv = *(float4*)&Bs[kk][tx * 4];
            unsigned long long bp0 = pack2(bv.x, bv.y);
            unsigned long long bp1 = pack2(bv.z, bv.w);
            float aa[4] = {av.x, av.y, av.z, av.w};
#pragma unroll
            for (int i = 0; i < 4; i++) {
                unsigned long long ap = pack2(aa[i], aa[i]);
                fma2u(acc[i][0], ap, bp0);
                fma2u(acc[i][1], ap, bp1);
            }
        }
    }

    int c  = c0 + tx * 4;   // permuted col of the i-gate; quad = (i,f,g,o)
    int jh = c >> 2;        // hidden unit
#pragma unroll
    for (int i = 0; i < 4; i++) {
        int n = n0 + ty * 4 + i;
        float rr = 1.0f - (float)is_init[n * T_S + t];
        float4 xw = *(const float4*)&g_xw[(size_t)(n * T_S + t) * G4 + c];
        float2 g01 = unpack2(acc[i][0]);
        float2 g23 = unpack2(acc[i][1]);
        float gi = g01.x + xw.x;
        float gf = g01.y + xw.y;
        float gg = g23.x + xw.z;
        float go = g23.y + xw.w;
        float cold = g_c[n * H_D + jh] * rr;
        float cn = sigf(gf) * cold + sigf(gi) * tanhf(gg);
        float hn = sigf(go) * tanhf(cn);
        g_c[n * H_D + jh]  = cn;
        hout[n * H_D + jh] = hn;
        g_hs[(size_t)(n * T_S + t) * H_D + jh] = hn;
    }
}

// ---------------- output GEMM: out = mish(hs @ Wout_t + b_out) -------------
__global__ __launch_bounds__(256) void gemm_out_kernel(const float* __restrict__ b_out,
                                                       float* __restrict__ out) {
    __shared__ float As[16][128];
    __shared__ float Bs[16][128];
    int tid = threadIdx.x;
    int m0 = blockIdx.y * 128;
    int n0 = blockIdx.x * 128;
    int ty = tid >> 4, tx = tid & 15;

    int arow = tid >> 2;
    int akq  = (tid & 3) * 4;
    int brow = tid >> 5;
    int bcol = (tid & 31) * 4;

    unsigned long long acc[8][4] = {};

    for (int k0 = 0; k0 < H_D; k0 += 16) {
        float4 a0 = *(const float4*)(g_hs + (size_t)(m0 + arow)      * H_D + k0 + akq);
        float4 a1 = *(const float4*)(g_hs + (size_t)(m0 + arow + 64) * H_D + k0 + akq);
        float4 b0 = *(const float4*)(g_Wout_t + (size_t)(k0 + brow)     * H_D + n0 + bcol);
        float4 b1 = *(const float4*)(g_Wout_t + (size_t)(k0 + brow + 8) * H_D + n0 + bcol);
        __syncthreads();
        As[akq + 0][arow] = a0.x; As[akq + 1][arow] = a0.y;
        As[akq + 2][arow] = a0.z; As[akq + 3][arow] = a0.w;
        As[akq + 0][arow + 64] = a1.x; As[akq + 1][arow + 64] = a1.y;
        As[akq + 2][arow + 64] = a1.z; As[akq + 3][arow + 64] = a1.w;
        *(float4*)&Bs[brow][bcol]     = b0;
        *(float4*)&Bs[brow + 8][bcol] = b1;
        __syncthreads();
#pragma unroll
        for (int kk = 0; kk < 16; kk++) {
            float4 aA = *(float4*)&As[kk][ty * 8];
            float4 aB = *(float4*)&As[kk][ty * 8 + 4];
            float4 bA = *(float4*)&Bs[kk][tx * 8];
            float4 bB = *(float4*)&Bs[kk][tx * 8 + 4];
            unsigned long long bp0 = pack2(bA.x, bA.y);
            unsigned long long bp1 = pack2(bA.z, bA.w);
            unsigned long long bp2 = pack2(bB.x, bB.y);
            unsigned long long bp3 = pack2(bB.z, bB.w);
            float av[8] = {aA.x, aA.y, aA.z, aA.w, aB.x, aB.y, aB.z, aB.w};
#pragma unroll
            for (int i = 0; i < 8; i++) {
                unsigned long long ap = pack2(av[i], av[i]);
                fma2u(acc[i][0], ap, bp0);
                fma2u(acc[i][1], ap, bp1);
                fma2u(acc[i][2], ap, bp2);
                fma2u(acc[i][3], ap, bp3);
            }
        }
    }
#pragma unroll
    for (int i = 0; i < 8; i++) {
        int m = m0 + ty * 8 + i;
#pragma unroll
        for (int j = 0; j < 4; j++) {
            float2 v = unpack2(acc[i][j]);
            int c = n0 + tx * 8 + j * 2;
            float v0 = v.x + b_out[c];
            float v1 = v.y + b_out[c + 1];
            // mish(x) = x * tanh(log1p(exp(x)))
            float o0 = v0 * tanhf(log1pf(expf(v0)));
            float o1 = v1 * tanhf(log1pf(expf(v1)));
            out[(size_t)m * H_D + c]     = o0;
            out[(size_t)m * H_D + c + 1] = o1;
        }
    }
}

// ---------------- broadcast hT, cT to [N,T,H] -------------------------------
__global__ void bcast_kernel(float* __restrict__ out) {
    int i = blockIdx.x * blockDim.x + threadIdx.x;   // over NT*H_D/4 float4s
    if (i < NT * H_D / 4) {
        int row = i >> 7;      // H_D/4 = 128 float4 per row; row = n*T+t
        int f4  = i & 127;
        int n   = row >> 7;    // T = 128
        float4 hv = *(const float4*)&g_h[0][n * H_D + f4 * 4];  // final h lives in buf 0 (T even)
        float4 cv = *(const float4*)&g_c[n * H_D + f4 * 4];
        float4* o = (float4*)out;
        o[(size_t)(NT * H_D / 4) + i]     = hv;
        o[(size_t)(NT * H_D / 4) * 2 + i] = cv;
    }
}

// ---------------- launch ----------------------------------------------------
extern "C" void kernel_launch(void* const* d_in, const int* in_sizes, int n_in,
                              void* d_out, int out_size) {
    const float* x      = (const float*)d_in[0];
    const int*   isinit = (const int*)  d_in[1];
    const float* hx     = (const float*)d_in[2];
    const float* cx     = (const float*)d_in[3];
    const float* W_ih   = (const float*)d_in[4];
    const float* W_hh   = (const float*)d_in[5];
    const float* b_ih   = (const float*)d_in[6];
    const float* b_hh   = (const float*)d_in[7];
    const float* W_out  = (const float*)d_in[8];
    const float* b_out  = (const float*)d_in[9];
    float* out = (float*)d_out;

    prep_kernel<<<(I_D * G4 + 255) / 256, 256>>>(W_ih, W_hh, b_ih, b_hh, W_out);
    init_kernel<<<(N_B * H_D + 255) / 256, 256>>>(hx, cx);

    { dim3 g(G4 / 128, NT / 128); gemm_xw_kernel<<<g, 256>>>(x); }

    for (int t = 0; t < T_S; t++) {
        dim3 g(G4 / 64, N_B / 64);
        lstm_step_kernel<<<g, 256>>>(isinit, t);
    }

    { dim3 g(H_D / 128, NT / 128); gemm_out_kernel<<<g, 256>>>(b_out, out); }

    bcast_kernel<<<(NT * H_D / 4 + 255) / 256, 256>>>(out);
}

// round 5
// speedup vs baseline: 1.2008x; 1.1559x over previous
#include <cuda_runtime.h>
#include <math.h>

// Problem dims (fixed by the dataset)
#define N_B 256
#define T_S 128
#define I_D 512
#define H_D 512
#define G4  2048            // 4*H
#define NT  32768           // N_B*T_S

#define NCTA 128            // persistent grid: 32 col-blocks x 4 batch-blocks

// ---------------- scratch (static device memory; no runtime allocs) --------
__device__ float g_xw[(size_t)NT * G4];     // x@W_ih^T + bias, gate-permuted (256MB)
__device__ float g_hs[(size_t)NT * H_D];    // all h_t (64MB)
__device__ float g_h[2][N_B * H_D];         // ping-pong hidden state
__device__ float g_c[N_B * H_D];            // cell state
__device__ float g_Wih_t[I_D * G4];         // W_ih^T, gate-permuted cols
__device__ float g_Whh_t[H_D * G4];         // W_hh^T, gate-permuted cols
__device__ float g_Wout_t[H_D * H_D];       // W_out^T
__device__ float g_bias[G4];                // (b_ih+b_hh), gate-permuted
__device__ unsigned g_bar;                  // grid barrier counter (reset each launch)

// ---------------- packed f32x2 FMA helpers ---------------------------------
__device__ __forceinline__ unsigned long long pack2(float x, float y) {
    unsigned long long r;
    asm("mov.b64 %0, {%1, %2};" : "=l"(r) : "f"(x), "f"(y));
    return r;
}
__device__ __forceinline__ void fma2u(unsigned long long &d,
                                      unsigned long long a,
                                      unsigned long long b) {
    asm("fma.rn.f32x2 %0, %1, %2, %0;" : "+l"(d) : "l"(a), "l"(b));
}
__device__ __forceinline__ float2 unpack2(unsigned long long v) {
    float2 r;
    asm("mov.b64 {%0, %1}, %2;" : "=f"(r.x), "=f"(r.y) : "l"(v));
    return r;
}

__device__ __forceinline__ float sigf(float x) { return 1.0f / (1.0f + expf(-x)); }

// ---------------- weight prep: transpose + gate-quadruple permutation ------
// permuted column p = 4*jh + g  <->  original gate row orig = g*H + jh
__global__ void prep_kernel(const float* __restrict__ W_ih,
                            const float* __restrict__ W_hh,
                            const float* __restrict__ b_ih,
                            const float* __restrict__ b_hh,
                            const float* __restrict__ W_out) {
    int i = blockIdx.x * blockDim.x + threadIdx.x;
    if (i < I_D * G4) {
        int k = i / G4, p = i % G4;
        int orig = (p & 3) * H_D + (p >> 2);
        g_Wih_t[i] = W_ih[(size_t)orig * I_D + k];
        g_Whh_t[i] = W_hh[(size_t)orig * H_D + k];
    }
    if (i < H_D * H_D) {
        int k = i / H_D, j = i % H_D;
        g_Wout_t[i] = W_out[(size_t)j * H_D + k];
    }
    if (i < G4) {
        int orig = (i & 3) * H_D + (i >> 2);
        g_bias[i] = b_ih[orig] + b_hh[orig];
    }
}

// ---------------- init h0, c0 from hx[:,0,:], cx[:,0,:]; reset barrier -----
__global__ void init_kernel(const float* __restrict__ hx,
                            const float* __restrict__ cx) {
    int i = blockIdx.x * blockDim.x + threadIdx.x;
    if (i == 0) g_bar = 0u;
    if (i < N_B * H_D) {
        int n = i / H_D, k = i % H_D;
        g_h[0][i] = hx[(size_t)n * T_S * H_D + k];
        g_c[i]    = cx[(size_t)n * T_S * H_D + k];
    }
}

// ---------------- pre-GEMM: g_xw = x @ Wih_t + bias (permuted cols) --------
// 128x128 tile, BK=16, 256 threads, 8x8 per thread via f32x2
__global__ __launch_bounds__(256) void gemm_xw_kernel(const float* __restrict__ x) {
    __shared__ float As[16][128];
    __shared__ float Bs[16][128];
    int tid = threadIdx.x;
    int m0 = blockIdx.y * 128;
    int n0 = blockIdx.x * 128;
    int ty = tid >> 4, tx = tid & 15;

    int arow = tid >> 2;          // 0..63 (second load +64)
    int akq  = (tid & 3) * 4;     // k offset 0,4,8,12
    int brow = tid >> 5;          // 0..7  (second load +8)
    int bcol = (tid & 31) * 4;    // 0..124

    unsigned long long acc[8][4] = {};

    for (int k0 = 0; k0 < I_D; k0 += 16) {
        float4 a0 = *(const float4*)(x + (size_t)(m0 + arow)      * I_D + k0 + akq);
        float4 a1 = *(const float4*)(x + (size_t)(m0 + arow + 64) * I_D + k0 + akq);
        float4 b0 = *(const float4*)(g_Wih_t + (size_t)(k0 + brow)     * G4 + n0 + bcol);
        float4 b1 = *(const float4*)(g_Wih_t + (size_t)(k0 + brow + 8) * G4 + n0 + bcol);
        __syncthreads();
        As[akq + 0][arow] = a0.x; As[akq + 1][arow] = a0.y;
        As[akq + 2][arow] = a0.z; As[akq + 3][arow] = a0.w;
        As[akq + 0][arow + 64] = a1.x; As[akq + 1][arow + 64] = a1.y;
        As[akq + 2][arow + 64] = a1.z; As[akq + 3][arow + 64] = a1.w;
        *(float4*)&Bs[brow][bcol]     = b0;
        *(float4*)&Bs[brow + 8][bcol] = b1;
        __syncthreads();
#pragma unroll
        for (int kk = 0; kk < 16; kk++) {
            float4 aA = *(float4*)&As[kk][ty * 8];
            float4 aB = *(float4*)&As[kk][ty * 8 + 4];
            float4 bA = *(float4*)&Bs[kk][tx * 8];
            float4 bB = *(float4*)&Bs[kk][tx * 8 + 4];
            unsigned long long bp0 = pack2(bA.x, bA.y);
            unsigned long long bp1 = pack2(bA.z, bA.w);
            unsigned long long bp2 = pack2(bB.x, bB.y);
            unsigned long long bp3 = pack2(bB.z, bB.w);
            float av[8] = {aA.x, aA.y, aA.z, aA.w, aB.x, aB.y, aB.z, aB.w};
#pragma unroll
            for (int i = 0; i < 8; i++) {
                unsigned long long ap = pack2(av[i], av[i]);
                fma2u(acc[i][0], ap, bp0);
                fma2u(acc[i][1], ap, bp1);
                fma2u(acc[i][2], ap, bp2);
                fma2u(acc[i][3], ap, bp3);
            }
        }
    }
#pragma unroll
    for (int i = 0; i < 8; i++) {
        int m = m0 + ty * 8 + i;
#pragma unroll
        for (int j = 0; j < 4; j++) {
            float2 v = unpack2(acc[i][j]);
            int c = n0 + tx * 8 + j * 2;
            v.x += g_bias[c];
            v.y += g_bias[c + 1];
            *(float2*)&g_xw[(size_t)m * G4 + c] = v;
        }
    }
}

// ---------------- persistent recurrence: all 128 timesteps in one kernel ---
// grid (32,4): b.x -> 64 gate-cols (16 hidden units), b.y -> 64 batch rows.
// W_hh slice (64 cols x 512 K = 128KB) lives in dynamic SMEM for the whole kernel.
// Per step: gates = (h*r) @ Whh + xw[:,t,:], then fused LSTM cell; grid barrier.
__global__ __launch_bounds__(256, 1) void lstm_persist_kernel(const int* __restrict__ is_init) {
    extern __shared__ float smem[];
    float* Ws   = smem;                 // [512][64]
    float* Ab0  = smem + 512 * 64;      // [16][64]
    float* Ab1  = Ab0 + 16 * 64;        // [16][64]

    const int tid = threadIdx.x;
    const int c0 = blockIdx.x * 64;     // gate cols (permuted)
    const int n0 = blockIdx.y * 64;     // batch
    const int ty = tid >> 4, tx = tid & 15;

    const int arow = tid >> 2;          // 0..63
    const int akq  = (tid & 3) * 4;     // k offset 0,4,8,12
    const int an   = n0 + arow;

    // ---- load W_hh slice into SMEM once: Ws[k][cl] = g_Whh_t[k*G4 + c0+cl]
    for (int i = tid; i < 512 * 16; i += 256) {
        int k  = i >> 4;
        int cl = (i & 15) * 4;
        *(float4*)&Ws[k * 64 + cl] =
            *(const float4*)(g_Whh_t + (size_t)k * G4 + c0 + cl);
    }
    __syncthreads();

    const int cc = c0 + tx * 4;         // permuted col of i-gate; quad=(i,f,g,o)
    const int jh = cc >> 2;             // hidden unit owned by this thread

    for (int t = 0; t < T_S; t++) {
        const float* hin  = g_h[t & 1];
        float*       hout = g_h[(t + 1) & 1];
        const float rr_a = 1.0f - (float)is_init[an * T_S + t];

        // prefetch + store chunk 0 into Ab0 (ld.cg: h ping-pong must bypass L1)
        {
            float4 a = __ldcg((const float4*)(hin + (size_t)an * H_D + akq));
            Ab0[(akq + 0) * 64 + arow] = a.x * rr_a;
            Ab0[(akq + 1) * 64 + arow] = a.y * rr_a;
            Ab0[(akq + 2) * 64 + arow] = a.z * rr_a;
            Ab0[(akq + 3) * 64 + arow] = a.w * rr_a;
        }
        __syncthreads();

        unsigned long long acc[4][2] = {};
        float* cur = Ab0;
        float* nxt = Ab1;

        for (int ch = 0; ch < 32; ch++) {
            float4 a;
            if (ch < 31)
                a = __ldcg((const float4*)(hin + (size_t)an * H_D + (ch + 1) * 16 + akq));

            const float* Wk = Ws + ch * 16 * 64;
#pragma unroll
            for (int kk = 0; kk < 16; kk++) {
                float4 av = *(const float4*)(cur + kk * 64 + ty * 4);
                float4 bv = *(const float4*)(Wk + kk * 64 + tx * 4);
                unsigned long long bp0 = pack2(bv.x, bv.y);
                unsigned long long bp1 = pack2(bv.z, bv.w);
                float aa[4] = {av.x, av.y, av.z, av.w};
#pragma unroll
                for (int i = 0; i < 4; i++) {
                    unsigned long long ap = pack2(aa[i], aa[i]);
                    fma2u(acc[i][0], ap, bp0);
                    fma2u(acc[i][1], ap, bp1);
                }
            }

            if (ch < 31) {
                nxt[(akq + 0) * 64 + arow] = a.x * rr_a;
                nxt[(akq + 1) * 64 + arow] = a.y * rr_a;
                nxt[(akq + 2) * 64 + arow] = a.z * rr_a;
                nxt[(akq + 3) * 64 + arow] = a.w * rr_a;
            }
            __syncthreads();
            float* tmp = cur; cur = nxt; nxt = tmp;
        }

        // ---- fused LSTM cell epilogue (this CTA owns (n-block, jh-block) of c)
#pragma unroll
        for (int i = 0; i < 4; i++) {
            int n = n0 + ty * 4 + i;
            float rr = 1.0f - (float)is_init[n * T_S + t];
            float4 xw = *(const float4*)&g_xw[(size_t)(n * T_S + t) * G4 + cc];
            float2 g01 = unpack2(acc[i][0]);
            float2 g23 = unpack2(acc[i][1]);
            float gi = g01.x + xw.x;
            float gf = g01.y + xw.y;
            float gg = g23.x + xw.z;
            float go = g23.y + xw.w;
            float cold = g_c[n * H_D + jh] * rr;
            float cn = sigf(gf) * cold + sigf(gi) * tanhf(gg);
            float hn = sigf(go) * tanhf(cn);
            g_c[n * H_D + jh]  = cn;
            hout[n * H_D + jh] = hn;
            g_hs[(size_t)(n * T_S + t) * H_D + jh] = hn;
        }

        // ---- grid barrier (monotonic counter; no reset races within launch)
        if (t < T_S - 1) {
            __syncthreads();
            if (tid == 0) {
                __threadfence();
                atomicAdd(&g_bar, 1u);
                unsigned target = (unsigned)NCTA * (unsigned)(t + 1);
                while (*(volatile unsigned*)&g_bar < target) { }
                __threadfence();
            }
            __syncthreads();
        }
    }
}

// ---------------- output GEMM: out = mish(hs @ Wout_t + b_out) -------------
__global__ __launch_bounds__(256) void gemm_out_kernel(const float* __restrict__ b_out,
                                                       float* __restrict__ out) {
    __shared__ float As[16][128];
    __shared__ float Bs[16][128];
    int tid = threadIdx.x;
    int m0 = blockIdx.y * 128;
    int n0 = blockIdx.x * 128;
    int ty = tid >> 4, tx = tid & 15;

    int arow = tid >> 2;
    int akq  = (tid & 3) * 4;
    int brow = tid >> 5;
    int bcol = (tid & 31) * 4;

    unsigned long long acc[8][4] = {};

    for (int k0 = 0; k0 < H_D; k0 += 16) {
        float4 a0 = *(const float4*)(g_hs + (size_t)(m0 + arow)      * H_D + k0 + akq);
        float4 a1 = *(const float4*)(g_hs + (size_t)(m0 + arow + 64) * H_D + k0 + akq);
        float4 b0 = *(const float4*)(g_Wout_t + (size_t)(k0 + brow)     * H_D + n0 + bcol);
        float4 b1 = *(const float4*)(g_Wout_t + (size_t)(k0 + brow + 8) * H_D + n0 + bcol);
        __syncthreads();
        As[akq + 0][arow] = a0.x; As[akq + 1][arow] = a0.y;
        As[akq + 2][arow] = a0.z; As[akq + 3][arow] = a0.w;
        As[akq + 0][arow + 64] = a1.x; As[akq + 1][arow + 64] = a1.y;
        As[akq + 2][arow + 64] = a1.z; As[akq + 3][arow + 64] = a1.w;
        *(float4*)&Bs[brow][bcol]     = b0;
        *(float4*)&Bs[brow + 8][bcol] = b1;
        __syncthreads();
#pragma unroll
        for (int kk = 0; kk < 16; kk++) {
            float4 aA = *(float4*)&As[kk][ty * 8];
            float4 aB = *(float4*)&As[kk][ty * 8 + 4];
            float4 bA = *(float4*)&Bs[kk][tx * 8];
            float4 bB = *(float4*)&Bs[kk][tx * 8 + 4];
            unsigned long long bp0 = pack2(bA.x, bA.y);
            unsigned long long bp1 = pack2(bA.z, bA.w);
            unsigned long long bp2 = pack2(bB.x, bB.y);
            unsigned long long bp3 = pack2(bB.z, bB.w);
            float av[8] = {aA.x, aA.y, aA.z, aA.w, aB.x, aB.y, aB.z, aB.w};
#pragma unroll
            for (int i = 0; i < 8; i++) {
                unsigned long long ap = pack2(av[i], av[i]);
                fma2u(acc[i][0], ap, bp0);
                fma2u(acc[i][1], ap, bp1);
                fma2u(acc[i][2], ap, bp2);
                fma2u(acc[i][3], ap, bp3);
            }
        }
    }
#pragma unroll
    for (int i = 0; i < 8; i++) {
        int m = m0 + ty * 8 + i;
#pragma unroll
        for (int j = 0; j < 4; j++) {
            float2 v = unpack2(acc[i][j]);
            int c = n0 + tx * 8 + j * 2;
            float v0 = v.x + b_out[c];
            float v1 = v.y + b_out[c + 1];
            // mish(x) = x * tanh(log1p(exp(x)))
            float o0 = v0 * tanhf(log1pf(expf(v0)));
            float o1 = v1 * tanhf(log1pf(expf(v1)));
            out[(size_t)m * H_D + c]     = o0;
            out[(size_t)m * H_D + c + 1] = o1;
        }
    }
}

// ---------------- broadcast hT, cT to [N,T,H] -------------------------------
__global__ void bcast_kernel(float* __restrict__ out) {
    int i = blockIdx.x * blockDim.x + threadIdx.x;   // over NT*H_D/4 float4s
    if (i < NT * H_D / 4) {
        int row = i >> 7;      // H_D/4 = 128 float4 per row; row = n*T+t
        int f4  = i & 127;
        int n   = row >> 7;    // T = 128
        float4 hv = *(const float4*)&g_h[0][n * H_D + f4 * 4];  // final h in buf 0 (T even)
        float4 cv = *(const float4*)&g_c[n * H_D + f4 * 4];
        float4* o = (float4*)out;
        o[(size_t)(NT * H_D / 4) + i]     = hv;
        o[(size_t)(NT * H_D / 4) * 2 + i] = cv;
    }
}

// ---------------- launch ----------------------------------------------------
extern "C" void kernel_launch(void* const* d_in, const int* in_sizes, int n_in,
                              void* d_out, int out_size) {
    const float* x      = (const float*)d_in[0];
    const int*   isinit = (const int*)  d_in[1];
    const float* hx     = (const float*)d_in[2];
    const float* cx     = (const float*)d_in[3];
    const float* W_ih   = (const float*)d_in[4];
    const float* W_hh   = (const float*)d_in[5];
    const float* b_ih   = (const float*)d_in[6];
    const float* b_hh   = (const float*)d_in[7];
    const float* W_out  = (const float*)d_in[8];
    const float* b_out  = (const float*)d_in[9];
    float* out = (float*)d_out;

    const int SMEM_BYTES = (512 * 64 + 2 * 16 * 64) * (int)sizeof(float);  // 139264
    cudaFuncSetAttribute(lstm_persist_kernel,
                         cudaFuncAttributeMaxDynamicSharedMemorySize, SMEM_BYTES);

    prep_kernel<<<(I_D * G4 + 255) / 256, 256>>>(W_ih, W_hh, b_ih, b_hh, W_out);
    init_kernel<<<(N_B * H_D + 255) / 256, 256>>>(hx, cx);

    { dim3 g(G4 / 128, NT / 128); gemm_xw_kernel<<<g, 256>>>(x); }

    { dim3 g(32, 4); lstm_persist_kernel<<<g, 256, SMEM_BYTES>>>(isinit); }

    { dim3 g(H_D / 128, NT / 128); gemm_out_kernel<<<g, 256>>>(b_out, out); }

    bcast_kernel<<<(NT * H_D / 4 + 255) / 256, 256>>>(out);
}